// round 2
// baseline (speedup 1.0000x reference)
#include <cuda_runtime.h>
#include <math.h>

#define NN      131072
#define DEG     16
#define NNZE    (NN*DEG)

// ---------------- scratch (static device globals; no allocation) ----------------
__device__ float  g_y [NN*32];        // x @ W1
__device__ float  g_h1[NN*32];        // relu(spmm(y)+b1)
__device__ float  g_h2[NN*64];        // relu(spmm(h1)@W2+b2)
__device__ int    g_cnt[NN];
__device__ int    g_rowptr[NN+1];
__device__ int    g_cursor[NN];
__device__ float2 g_packed[NNZE];     // (col as int-bits, val), grouped by row

// ---------------- CSR build ----------------
__global__ void k_zero_cnt() {
    int i = blockIdx.x*blockDim.x + threadIdx.x;
    if (i < NN) g_cnt[i] = 0;
}

__global__ void k_hist(const int* __restrict__ rows) {
    int e = blockIdx.x*blockDim.x + threadIdx.x;
    if (e < NNZE) atomicAdd(&g_cnt[rows[e]], 1);
}

__global__ void k_scan() {
    __shared__ int ss[1024];
    int t = threadIdx.x;
    int base = t * 128;                 // 1024 threads * 128 rows = NN
    int s = 0;
    for (int i = 0; i < 128; i++) s += g_cnt[base+i];
    ss[t] = s;
    __syncthreads();
    for (int off = 1; off < 1024; off <<= 1) {
        int v = (t >= off) ? ss[t-off] : 0;
        __syncthreads();
        ss[t] += v;
        __syncthreads();
    }
    int run = (t == 0) ? 0 : ss[t-1];
    for (int i = 0; i < 128; i++) {
        g_rowptr[base+i] = run;
        g_cursor[base+i] = run;
        run += g_cnt[base+i];
    }
    if (t == 1023) g_rowptr[NN] = run;
}

__global__ void k_scatter(const int* __restrict__ rows, const int* __restrict__ cols,
                          const float* __restrict__ vals) {
    int e = blockIdx.x*blockDim.x + threadIdx.x;
    if (e < NNZE) {
        int r = rows[e];
        int pos = atomicAdd(&g_cursor[r], 1);
        g_packed[pos] = make_float2(__int_as_float(cols[e]), vals[e]);
    }
}

// ---------------- y = x @ W1  (project 128->32 BEFORE the SpMM; linearity) -------
__global__ void __launch_bounds__(256) k_xw1(const float* __restrict__ x,
                                             const float* __restrict__ W1) {
    __shared__ float sW[128*32];
    int t = threadIdx.x;
    for (int i = t; i < 1024; i += 256) ((float4*)sW)[i] = ((const float4*)W1)[i];
    __syncthreads();
    int row = blockIdx.x*256 + t;
    const float4* xr = (const float4*)(x + (size_t)row*128);
    float acc[32];
    #pragma unroll
    for (int j = 0; j < 32; j++) acc[j] = 0.f;
    #pragma unroll 8
    for (int k4 = 0; k4 < 32; k4++) {
        float4 xv = xr[k4];
        #pragma unroll
        for (int c = 0; c < 4; c++) {
            float xk = (c==0) ? xv.x : (c==1) ? xv.y : (c==2) ? xv.z : xv.w;
            const float4* wr = (const float4*)(sW + (k4*4+c)*32);
            #pragma unroll
            for (int j4 = 0; j4 < 8; j4++) {
                float4 wv = wr[j4];
                acc[4*j4+0] += xk*wv.x; acc[4*j4+1] += xk*wv.y;
                acc[4*j4+2] += xk*wv.z; acc[4*j4+3] += xk*wv.w;
            }
        }
    }
    float4* yo = (float4*)(g_y + (size_t)row*32);
    #pragma unroll
    for (int j4 = 0; j4 < 8; j4++)
        yo[j4] = make_float4(acc[4*j4], acc[4*j4+1], acc[4*j4+2], acc[4*j4+3]);
}

// ---------------- SpMM 1: h1 = relu(spmm(y) + b1)  (warp per row) ----------------
__global__ void __launch_bounds__(256) k_spmm1(const float* __restrict__ b1) {
    int w = (blockIdx.x*256 + threadIdx.x) >> 5;
    int lane = threadIdx.x & 31;
    int s = g_rowptr[w], e = g_rowptr[w+1];
    float acc = 0.f;
    for (int i = s; i < e; i++) {
        float2 p = g_packed[i];                            // 8B broadcast
        acc += p.y * g_y[__float_as_int(p.x)*32 + lane];   // coalesced 128B gather
    }
    g_h1[w*32 + lane] = fmaxf(acc + b1[lane], 0.f);
}

// ---------------- SpMM 2 fused with @W2: h2 = relu(spmm(h1)@W2 + b2) -------------
__global__ void __launch_bounds__(256) k_spmm2(const float* __restrict__ W2,
                                               const float* __restrict__ b2) {
    __shared__ float sW[32*64];
    __shared__ float sz[8][33];
    int t = threadIdx.x;
    for (int i = t; i < 512; i += 256) ((float4*)sW)[i] = ((const float4*)W2)[i];
    __syncthreads();
    int w = (blockIdx.x*256 + t) >> 5;
    int wl = t >> 5, lane = t & 31;
    int s = g_rowptr[w], e = g_rowptr[w+1];
    float acc = 0.f;
    for (int i = s; i < e; i++) {
        float2 p = g_packed[i];
        acc += p.y * g_h1[__float_as_int(p.x)*32 + lane];
    }
    sz[wl][lane] = acc;
    __syncwarp();
    float o0 = b2[lane], o1 = b2[lane+32];
    #pragma unroll
    for (int k = 0; k < 32; k++) {
        float zv = sz[wl][k];
        o0 += zv * sW[k*64 + lane];
        o1 += zv * sW[k*64 + lane + 32];
    }
    size_t off = (size_t)w * 64;
    g_h2[off + lane]      = fmaxf(o0, 0.f);
    g_h2[off + lane + 32] = fmaxf(o1, 0.f);
}

// ---------------- fused transformer block + classifier + log_softmax -------------
// smem: [0, 12288) weight scratch | [12288, ...) K(256x64) V(256x64)  /  H(256x133)
#define SW_FLOATS   12288
#define SH_STRIDE   133                      // odd stride: conflict-free FFN rows
#define SMEM_FLOATS (SW_FLOATS + 256*SH_STRIDE)
#define SMEM_BYTES  (SMEM_FLOATS*4)

__device__ __forceinline__ void gemm_chunk32(const float* xin,
                                             const float* __restrict__ sw, int wstride,
                                             int coff, float (&acc)[32]) {
    #pragma unroll
    for (int k = 0; k < 64; k++) {
        float xv = xin[k];
        const float4* wr = (const float4*)(sw + k*wstride + coff);
        #pragma unroll
        for (int j4 = 0; j4 < 8; j4++) {
            float4 wv = wr[j4];
            acc[4*j4+0] += xv*wv.x; acc[4*j4+1] += xv*wv.y;
            acc[4*j4+2] += xv*wv.z; acc[4*j4+3] += xv*wv.w;
        }
    }
}

__device__ __forceinline__ void layernorm64(float (&v)[64], const float* __restrict__ g,
                                            const float* __restrict__ b) {
    float mu = 0.f;
    #pragma unroll
    for (int j = 0; j < 64; j++) mu += v[j];
    mu *= (1.f/64.f);
    float var = 0.f;
    #pragma unroll
    for (int j = 0; j < 64; j++) { float d = v[j]-mu; var += d*d; }
    var *= (1.f/64.f);
    float inv = rsqrtf(var + 1e-5f);
    #pragma unroll
    for (int j = 0; j < 64; j++) v[j] = (v[j]-mu)*inv*g[j] + b[j];
}

__global__ void __launch_bounds__(256) k_tr(
    const float* __restrict__ Wqkv, const float* __restrict__ bqkv,
    const float* __restrict__ Wo,   const float* __restrict__ bo,
    const float* __restrict__ g1,   const float* __restrict__ be1,
    const float* __restrict__ Wf1,  const float* __restrict__ bf1,
    const float* __restrict__ Wf2,  const float* __restrict__ bf2,
    const float* __restrict__ g2,   const float* __restrict__ be2,
    const float* __restrict__ Wc,   const float* __restrict__ bc,
    float* __restrict__ out)
{
    extern __shared__ float sm[];
    float* sw = sm;                      // 12288 floats of weight scratch
    float* sK = sm + SW_FLOATS;          // 256x64
    float* sV = sK + 256*64;             // 256x64
    float* sH = sm + SW_FLOATS;          // 256x133, reuses K/V region post-attention
    int t = threadIdx.x;
    int blk = blockIdx.x;
    const float4* xr4 = (const float4*)(g_h2 + ((size_t)blk*256 + t)*64);

    // ---- stage W_qkv (64x192 = 12288 floats = 3072 float4) ----
    for (int i = t; i < 3072; i += 256) ((float4*)sw)[i] = ((const float4*)Wqkv)[i];
    __syncthreads();

    // ---- phase 1: qkv = x @ W_qkv + b  (q -> regs, K/V -> smem) ----
    float q[64];
    #pragma unroll
    for (int ch = 0; ch < 6; ch++) {
        float acc[32];
        #pragma unroll
        for (int j = 0; j < 32; j++) acc[j] = bqkv[ch*32 + j];
        #pragma unroll
        for (int k4 = 0; k4 < 16; k4++) {
            float4 xv = xr4[k4];
            #pragma unroll
            for (int c = 0; c < 4; c++) {
                float xk = (c==0) ? xv.x : (c==1) ? xv.y : (c==2) ? xv.z : xv.w;
                const float4* wr = (const float4*)(sw + (k4*4+c)*192 + ch*32);
                #pragma unroll
                for (int j4 = 0; j4 < 8; j4++) {
                    float4 wv = wr[j4];
                    acc[4*j4+0] += xk*wv.x; acc[4*j4+1] += xk*wv.y;
                    acc[4*j4+2] += xk*wv.z; acc[4*j4+3] += xk*wv.w;
                }
            }
        }
        if (ch < 2) {
            #pragma unroll
            for (int j = 0; j < 32; j++) q[ch*32 + j] = acc[j];
        } else {
            float* dst = (ch < 4) ? (sK + t*64 + (ch-2)*32) : (sV + t*64 + (ch-4)*32);
            #pragma unroll
            for (int j4 = 0; j4 < 8; j4++)
                ((float4*)dst)[j4] = make_float4(acc[4*j4], acc[4*j4+1], acc[4*j4+2], acc[4*j4+3]);
        }
    }
    __syncthreads();

    // stage W_o early (sw region; disjoint from K/V). Post-attn barrier covers it.
    for (int i = t; i < 1024; i += 256) ((float4*)sw)[i] = ((const float4*)Wo)[i];

    // ---- phase 2: attention, per-thread query, 2-pass max-shifted softmax ----
    float o[64];
    #pragma unroll
    for (int h = 0; h < 4; h++) {
        float m = -1e30f;
        for (int kk = 0; kk < 256; kk++) {
            const float4* kp = (const float4*)(sK + kk*64 + h*16);
            float s = 0.f;
            #pragma unroll
            for (int d4 = 0; d4 < 4; d4++) {
                float4 kv = kp[d4];
                s += q[h*16+4*d4+0]*kv.x + q[h*16+4*d4+1]*kv.y
                   + q[h*16+4*d4+2]*kv.z + q[h*16+4*d4+3]*kv.w;
            }
            m = fmaxf(m, s);
        }
        float l = 0.f;
        float ctx[16];
        #pragma unroll
        for (int d = 0; d < 16; d++) ctx[d] = 0.f;
        for (int kk = 0; kk < 256; kk++) {
            const float4* kp = (const float4*)(sK + kk*64 + h*16);
            float s = 0.f;
            #pragma unroll
            for (int d4 = 0; d4 < 4; d4++) {
                float4 kv = kp[d4];
                s += q[h*16+4*d4+0]*kv.x + q[h*16+4*d4+1]*kv.y
                   + q[h*16+4*d4+2]*kv.z + q[h*16+4*d4+3]*kv.w;
            }
            float p = __expf((s - m) * 0.25f);   // /sqrt(16)
            l += p;
            const float4* vp = (const float4*)(sV + kk*64 + h*16);
            #pragma unroll
            for (int d4 = 0; d4 < 4; d4++) {
                float4 vv = vp[d4];
                ctx[4*d4+0] += p*vv.x; ctx[4*d4+1] += p*vv.y;
                ctx[4*d4+2] += p*vv.z; ctx[4*d4+3] += p*vv.w;
            }
        }
        float inv = 1.f / l;
        #pragma unroll
        for (int d = 0; d < 16; d++) o[h*16 + d] = ctx[d] * inv;
    }
    __syncthreads();   // W_o visible; all threads done with K/V

    // ---- a = o @ W_o + b_o;  x1 = LN1(x + a) ----
    float x1[64];
    #pragma unroll
    for (int ch = 0; ch < 2; ch++) {
        float acc[32];
        #pragma unroll
        for (int j = 0; j < 32; j++) acc[j] = bo[ch*32 + j];
        gemm_chunk32(o, sw, 64, ch*32, acc);
        #pragma unroll
        for (int j = 0; j < 32; j++) x1[ch*32 + j] = acc[j];
    }
    #pragma unroll
    for (int k4 = 0; k4 < 16; k4++) {     // residual: reload input (L2-hot)
        float4 xv = xr4[k4];
        x1[4*k4+0] += xv.x; x1[4*k4+1] += xv.y; x1[4*k4+2] += xv.z; x1[4*k4+3] += xv.w;
    }
    layernorm64(x1, g1, be1);
    __syncthreads();

    // ---- FFN up: h = gelu(x1 @ W_ff1 + b_ff1) -> own smem row ----
    for (int i = t; i < 2048; i += 256) ((float4*)sw)[i] = ((const float4*)Wf1)[i];
    __syncthreads();
    float* hrow = sH + t*SH_STRIDE;
    #pragma unroll
    for (int ch = 0; ch < 4; ch++) {
        float acc[32];
        #pragma unroll
        for (int j = 0; j < 32; j++) acc[j] = bf1[ch*32 + j];
        gemm_chunk32(x1, sw, 128, ch*32, acc);
        #pragma unroll
        for (int j = 0; j < 32; j++) {
            float v = acc[j];
            hrow[ch*32 + j] = 0.5f * v * (1.f + erff(v * 0.70710678118654752f));
        }
    }
    __syncthreads();

    // ---- FFN down + residual + LN2 ----
    for (int i = t; i < 2048; i += 256) ((float4*)sw)[i] = ((const float4*)Wf2)[i];
    __syncthreads();
    float x2[64];
    #pragma unroll
    for (int ch = 0; ch < 2; ch++) {
        float acc[32];
        #pragma unroll
        for (int j = 0; j < 32; j++) acc[j] = bf2[ch*32 + j];
        #pragma unroll 4
        for (int k = 0; k < 128; k++) {
            float hv = hrow[k];
            const float4* wr = (const float4*)(sw + k*64 + ch*32);
            #pragma unroll
            for (int j4 = 0; j4 < 8; j4++) {
                float4 wv = wr[j4];
                acc[4*j4+0] += hv*wv.x; acc[4*j4+1] += hv*wv.y;
                acc[4*j4+2] += hv*wv.z; acc[4*j4+3] += hv*wv.w;
            }
        }
        #pragma unroll
        for (int j = 0; j < 32; j++) x2[ch*32 + j] = acc[j] + x1[ch*32 + j];
    }
    layernorm64(x2, g2, be2);
    __syncthreads();

    // ---- classifier + log_softmax ----
    for (int i = t; i < 256; i += 256) ((float4*)sw)[i] = ((const float4*)Wc)[i];
    __syncthreads();
    float lg[16];
    #pragma unroll
    for (int j = 0; j < 16; j++) lg[j] = bc[j];
    #pragma unroll
    for (int k = 0; k < 64; k++) {
        float xv = x2[k];
        const float4* wr = (const float4*)(sw + k*16);
        #pragma unroll
        for (int j4 = 0; j4 < 4; j4++) {
            float4 wv = wr[j4];
            lg[4*j4+0] += xv*wv.x; lg[4*j4+1] += xv*wv.y;
            lg[4*j4+2] += xv*wv.z; lg[4*j4+3] += xv*wv.w;
        }
    }
    float mm = lg[0];
    #pragma unroll
    for (int j = 1; j < 16; j++) mm = fmaxf(mm, lg[j]);
    float ssum = 0.f;
    #pragma unroll
    for (int j = 0; j < 16; j++) ssum += __expf(lg[j] - mm);
    float lse = mm + logf(ssum);
    float4* op = (float4*)(out + ((size_t)blk*256 + t)*16);
    #pragma unroll
    for (int j4 = 0; j4 < 4; j4++)
        op[j4] = make_float4(lg[4*j4]-lse, lg[4*j4+1]-lse, lg[4*j4+2]-lse, lg[4*j4+3]-lse);
}

// ---------------- launch ----------------
extern "C" void kernel_launch(void* const* d_in, const int* in_sizes, int n_in,
                              void* d_out, int out_size) {
    const float* x    = (const float*)d_in[0];
    const int*   rows = (const int*)  d_in[1];
    const int*   cols = (const int*)  d_in[2];
    const float* vals = (const float*)d_in[3];
    const float* W1   = (const float*)d_in[4];
    const float* b1   = (const float*)d_in[5];
    const float* W2   = (const float*)d_in[6];
    const float* b2   = (const float*)d_in[7];
    const float* Wqkv = (const float*)d_in[8];
    const float* bqkv = (const float*)d_in[9];
    const float* Wo   = (const float*)d_in[10];
    const float* bo   = (const float*)d_in[11];
    const float* g1   = (const float*)d_in[12];
    const float* be1  = (const float*)d_in[13];
    const float* Wf1  = (const float*)d_in[14];
    const float* bf1  = (const float*)d_in[15];
    const float* Wf2  = (const float*)d_in[16];
    const float* bf2  = (const float*)d_in[17];
    const float* g2   = (const float*)d_in[18];
    const float* be2  = (const float*)d_in[19];
    const float* Wc   = (const float*)d_in[20];
    const float* bc   = (const float*)d_in[21];
    float* out = (float*)d_out;

    static bool attr_set = false;
    if (!attr_set) {
        cudaFuncSetAttribute(k_tr, cudaFuncAttributeMaxDynamicSharedMemorySize, SMEM_BYTES);
        attr_set = true;
    }

    k_zero_cnt<<<NN/256, 256>>>();
    k_hist    <<<NNZE/256, 256>>>(rows);
    k_scan    <<<1, 1024>>>();
    k_scatter <<<NNZE/256, 256>>>(rows, cols, vals);
    k_xw1     <<<NN/256, 256>>>(x, W1);
    k_spmm1   <<<NN/8, 256>>>(b1);
    k_spmm2   <<<NN/8, 256>>>(W2, b2);
    k_tr      <<<NN/256, 256, SMEM_BYTES>>>(Wqkv, bqkv, Wo, bo, g1, be1,
                                            Wf1, bf1, Wf2, bf2, g2, be2,
                                            Wc, bc, out);
}

// round 3
// speedup vs baseline: 1.1744x; 1.1744x over previous
#include <cuda_runtime.h>
#include <math.h>

#define NN      131072
#define DEG     16
#define NNZE    (NN*DEG)

typedef unsigned long long ull;

// ---- packed f32x2 helpers (Blackwell FFMA2; bit-identical fp32 math) ----
__device__ __forceinline__ ull ffma2(ull a, ull b, ull c) {
    ull d; asm("fma.rn.f32x2 %0, %1, %2, %3;" : "=l"(d) : "l"(a), "l"(b), "l"(c)); return d;
}
__device__ __forceinline__ ull fmul2(ull a, ull b) {
    ull d; asm("mul.rn.f32x2 %0, %1, %2;" : "=l"(d) : "l"(a), "l"(b)); return d;
}
__device__ __forceinline__ ull pack2(float x) {
    ull r; asm("mov.b64 %0, {%1, %1};" : "=l"(r) : "f"(x)); return r;
}
__device__ __forceinline__ float2 unpack2(ull a) {
    float lo, hi; asm("mov.b64 {%0, %1}, %2;" : "=f"(lo), "=f"(hi) : "l"(a));
    return make_float2(lo, hi);
}

// ---------------- scratch (static device globals; no allocation) ----------------
__device__ float  g_y [NN*32];
__device__ float  g_h1[NN*32];
__device__ float  g_h2[NN*64];
__device__ int    g_cnt[NN];
__device__ int    g_rowptr[NN+1];
__device__ int    g_cursor[NN];
__device__ float2 g_packed[NNZE];

// ---------------- CSR build ----------------
__global__ void k_zero_cnt() {
    int i = blockIdx.x*blockDim.x + threadIdx.x;
    if (i < NN) g_cnt[i] = 0;
}

__global__ void k_hist(const int* __restrict__ rows) {
    int e = blockIdx.x*blockDim.x + threadIdx.x;
    if (e < NNZE) atomicAdd(&g_cnt[rows[e]], 1);
}

__global__ void k_scan() {
    __shared__ int ss[1024];
    int t = threadIdx.x;
    int base = t * 128;
    int s = 0;
    for (int i = 0; i < 128; i++) s += g_cnt[base+i];
    ss[t] = s;
    __syncthreads();
    for (int off = 1; off < 1024; off <<= 1) {
        int v = (t >= off) ? ss[t-off] : 0;
        __syncthreads();
        ss[t] += v;
        __syncthreads();
    }
    int run = (t == 0) ? 0 : ss[t-1];
    for (int i = 0; i < 128; i++) {
        g_rowptr[base+i] = run;
        g_cursor[base+i] = run;
        run += g_cnt[base+i];
    }
    if (t == 1023) g_rowptr[NN] = run;
}

__global__ void k_scatter(const int* __restrict__ rows, const int* __restrict__ cols,
                          const float* __restrict__ vals) {
    int e = blockIdx.x*blockDim.x + threadIdx.x;
    if (e < NNZE) {
        int r = rows[e];
        int pos = atomicAdd(&g_cursor[r], 1);
        g_packed[pos] = make_float2(__int_as_float(cols[e]), vals[e]);
    }
}

// ---------------- y = x @ W1  (project 128->32 BEFORE SpMM; packed FMA) ----------
__global__ void __launch_bounds__(256) k_xw1(const float* __restrict__ x,
                                             const float* __restrict__ W1) {
    __shared__ float sW[128*32];
    int t = threadIdx.x;
    for (int i = t; i < 1024; i += 256) ((float4*)sW)[i] = ((const float4*)W1)[i];
    __syncthreads();
    int row = blockIdx.x*256 + t;
    const float4* xr = (const float4*)(x + (size_t)row*128);
    ull acc[16];
    #pragma unroll
    for (int j = 0; j < 16; j++) acc[j] = 0ull;      // (0.f, 0.f)
    #pragma unroll 4
    for (int k4 = 0; k4 < 32; k4++) {
        float4 xv = xr[k4];
        #pragma unroll
        for (int c = 0; c < 4; c++) {
            float xk = (c==0) ? xv.x : (c==1) ? xv.y : (c==2) ? xv.z : xv.w;
            ull xp = pack2(xk);
            const ulonglong2* wr = (const ulonglong2*)(sW + (k4*4+c)*32);
            #pragma unroll
            for (int j = 0; j < 8; j++) {
                ulonglong2 w = wr[j];
                acc[2*j+0] = ffma2(xp, w.x, acc[2*j+0]);
                acc[2*j+1] = ffma2(xp, w.y, acc[2*j+1]);
            }
        }
    }
    ulonglong2* yo = (ulonglong2*)(g_y + (size_t)row*32);
    #pragma unroll
    for (int j = 0; j < 8; j++) {
        ulonglong2 u; u.x = acc[2*j]; u.y = acc[2*j+1];
        yo[j] = u;
    }
}

// ---------------- SpMM 1: h1 = relu(spmm(y) + b1)  (warp per row) ----------------
__global__ void __launch_bounds__(256) k_spmm1(const float* __restrict__ b1) {
    int w = (blockIdx.x*256 + threadIdx.x) >> 5;
    int lane = threadIdx.x & 31;
    int s = g_rowptr[w], e = g_rowptr[w+1];
    float acc = 0.f;
    for (int i = s; i < e; i++) {
        float2 p = g_packed[i];
        acc += p.y * g_y[__float_as_int(p.x)*32 + lane];
    }
    g_h1[w*32 + lane] = fmaxf(acc + b1[lane], 0.f);
}

// ---------------- SpMM 2 fused with @W2: h2 = relu(spmm(h1)@W2 + b2) -------------
__global__ void __launch_bounds__(256) k_spmm2(const float* __restrict__ W2,
                                               const float* __restrict__ b2) {
    __shared__ float sW[32*64];
    __shared__ float sz[8][33];
    int t = threadIdx.x;
    for (int i = t; i < 512; i += 256) ((float4*)sW)[i] = ((const float4*)W2)[i];
    __syncthreads();
    int w = (blockIdx.x*256 + t) >> 5;
    int wl = t >> 5, lane = t & 31;
    int s = g_rowptr[w], e = g_rowptr[w+1];
    float acc = 0.f;
    for (int i = s; i < e; i++) {
        float2 p = g_packed[i];
        acc += p.y * g_h1[__float_as_int(p.x)*32 + lane];
    }
    sz[wl][lane] = acc;
    __syncwarp();
    float o0 = b2[lane], o1 = b2[lane+32];
    #pragma unroll
    for (int k = 0; k < 32; k++) {
        float zv = sz[wl][k];
        o0 += zv * sW[k*64 + lane];
        o1 += zv * sW[k*64 + lane + 32];
    }
    size_t off = (size_t)w * 64;
    g_h2[off + lane]      = fmaxf(o0, 0.f);
    g_h2[off + lane + 32] = fmaxf(o1, 0.f);
}

// ---------------- fused transformer block + classifier + log_softmax -------------
#define SW_FLOATS   12288
#define KV_STRIDE   68                       // 68 mod 32 = 4 -> 4-way instead of 32-way STS conflicts
#define SH_STRIDE   133
#define SMEM_FLOATS (SW_FLOATS + 2*256*KV_STRIDE)
#define SMEM_BYTES  (SMEM_FLOATS*4)

// packed GEMM: 64-deep K, 32 output cols (16 pairs), weights in smem
__device__ __forceinline__ void gemm64p(const float* xin,
                                        const float* __restrict__ sw, int ws,
                                        int coff, ull (&acc)[16]) {
    #pragma unroll
    for (int k = 0; k < 64; k++) {
        ull xp = pack2(xin[k]);
        const ulonglong2* wr = (const ulonglong2*)(sw + k*ws + coff);
        #pragma unroll
        for (int j = 0; j < 8; j++) {
            ulonglong2 w = wr[j];
            acc[2*j+0] = ffma2(xp, w.x, acc[2*j+0]);
            acc[2*j+1] = ffma2(xp, w.y, acc[2*j+1]);
        }
    }
}

__device__ __forceinline__ void layernorm64(float (&v)[64], const float* __restrict__ g,
                                            const float* __restrict__ b) {
    float mu = 0.f;
    #pragma unroll
    for (int j = 0; j < 64; j++) mu += v[j];
    mu *= (1.f/64.f);
    float var = 0.f;
    #pragma unroll
    for (int j = 0; j < 64; j++) { float d = v[j]-mu; var += d*d; }
    var *= (1.f/64.f);
    float inv = rsqrtf(var + 1e-5f);
    #pragma unroll
    for (int j = 0; j < 64; j++) v[j] = (v[j]-mu)*inv*g[j] + b[j];
}

__global__ void __launch_bounds__(256) k_tr(
    const float* __restrict__ Wqkv, const float* __restrict__ bqkv,
    const float* __restrict__ Wo,   const float* __restrict__ bo,
    const float* __restrict__ g1,   const float* __restrict__ be1,
    const float* __restrict__ Wf1,  const float* __restrict__ bf1,
    const float* __restrict__ Wf2,  const float* __restrict__ bf2,
    const float* __restrict__ g2,   const float* __restrict__ be2,
    const float* __restrict__ Wc,   const float* __restrict__ bc,
    float* __restrict__ out)
{
    extern __shared__ float sm[];
    float* sw = sm;                              // 12288-float weight scratch
    float* sK = sm + SW_FLOATS;                  // 256 x 68
    float* sV = sK + 256*KV_STRIDE;              // 256 x 68
    float* sH = sm + SW_FLOATS;                  // 256 x 133, reuses K/V post-attention
    int t = threadIdx.x;
    int blk = blockIdx.x;
    const float4* xr4 = (const float4*)(g_h2 + ((size_t)blk*256 + t)*64);

    // ---- stage W_qkv (64x192) ----
    for (int i = t; i < 3072; i += 256) ((float4*)sw)[i] = ((const float4*)Wqkv)[i];
    __syncthreads();

    // ---- phase 1: qkv projection; q stays packed in regs, K/V -> smem ----
    ull q2[32];
    #pragma unroll
    for (int ch = 0; ch < 6; ch++) {
        ull acc[16];
        const ull* bp = (const ull*)(bqkv + ch*32);
        #pragma unroll
        for (int j = 0; j < 16; j++) acc[j] = bp[j];
        #pragma unroll
        for (int k4 = 0; k4 < 16; k4++) {
            float4 xv = xr4[k4];
            #pragma unroll
            for (int c = 0; c < 4; c++) {
                float xk = (c==0) ? xv.x : (c==1) ? xv.y : (c==2) ? xv.z : xv.w;
                ull xp = pack2(xk);
                const ulonglong2* wr = (const ulonglong2*)(sw + (k4*4+c)*192 + ch*32);
                #pragma unroll
                for (int j = 0; j < 8; j++) {
                    ulonglong2 w = wr[j];
                    acc[2*j+0] = ffma2(xp, w.x, acc[2*j+0]);
                    acc[2*j+1] = ffma2(xp, w.y, acc[2*j+1]);
                }
            }
        }
        if (ch < 2) {
            #pragma unroll
            for (int j = 0; j < 16; j++) q2[ch*16 + j] = acc[j];
        } else {
            float* dst = (ch < 4) ? (sK + t*KV_STRIDE + (ch-2)*32)
                                  : (sV + t*KV_STRIDE + (ch-4)*32);
            #pragma unroll
            for (int j = 0; j < 8; j++) {
                ulonglong2 u; u.x = acc[2*j]; u.y = acc[2*j+1];
                ((ulonglong2*)dst)[j] = u;
            }
        }
    }
    __syncthreads();

    // stage W_o early (sw region; disjoint from K/V); post-attn barrier covers it
    for (int i = t; i < 1024; i += 256) ((float4*)sw)[i] = ((const float4*)Wo)[i];

    // ---- phase 2: attention, 2-pass max-shifted softmax, packed dot/ctx ----
    float o[64];
    #pragma unroll
    for (int h = 0; h < 4; h++) {
        float m = -1e30f;
        for (int kk = 0; kk < 256; kk++) {
            const ulonglong2* kp = (const ulonglong2*)(sK + kk*KV_STRIDE + h*16);
            ull s2 = 0ull;
            #pragma unroll
            for (int d = 0; d < 4; d++) {
                ulonglong2 kv = kp[d];
                s2 = ffma2(q2[h*8 + 2*d + 0], kv.x, s2);
                s2 = ffma2(q2[h*8 + 2*d + 1], kv.y, s2);
            }
            float2 sp = unpack2(s2);
            m = fmaxf(m, sp.x + sp.y);
        }
        float l = 0.f;
        ull ctx[8];
        #pragma unroll
        for (int d = 0; d < 8; d++) ctx[d] = 0ull;
        for (int kk = 0; kk < 256; kk++) {
            const ulonglong2* kp = (const ulonglong2*)(sK + kk*KV_STRIDE + h*16);
            ull s2 = 0ull;
            #pragma unroll
            for (int d = 0; d < 4; d++) {
                ulonglong2 kv = kp[d];
                s2 = ffma2(q2[h*8 + 2*d + 0], kv.x, s2);
                s2 = ffma2(q2[h*8 + 2*d + 1], kv.y, s2);
            }
            float2 sp = unpack2(s2);
            float p = __expf((sp.x + sp.y - m) * 0.25f);   // /sqrt(16)
            l += p;
            ull pp = pack2(p);
            const ulonglong2* vp = (const ulonglong2*)(sV + kk*KV_STRIDE + h*16);
            #pragma unroll
            for (int d = 0; d < 4; d++) {
                ulonglong2 vv = vp[d];
                ctx[2*d+0] = ffma2(pp, vv.x, ctx[2*d+0]);
                ctx[2*d+1] = ffma2(pp, vv.y, ctx[2*d+1]);
            }
        }
        ull inv2 = pack2(1.f / l);
        #pragma unroll
        for (int d = 0; d < 8; d++) {
            float2 c = unpack2(fmul2(ctx[d], inv2));
            o[h*16 + 2*d + 0] = c.x;
            o[h*16 + 2*d + 1] = c.y;
        }
    }
    __syncthreads();   // W_o visible; everyone done with K/V

    // ---- a = o @ W_o + b_o;  x1 = LN1(x + a) ----
    float x1[64];
    #pragma unroll
    for (int ch = 0; ch < 2; ch++) {
        ull acc[16];
        const ull* bp = (const ull*)(bo + ch*32);
        #pragma unroll
        for (int j = 0; j < 16; j++) acc[j] = bp[j];
        gemm64p(o, sw, 64, ch*32, acc);
        #pragma unroll
        for (int j = 0; j < 16; j++) {
            float2 v = unpack2(acc[j]);
            x1[ch*32 + 2*j + 0] = v.x;
            x1[ch*32 + 2*j + 1] = v.y;
        }
    }
    #pragma unroll
    for (int k4 = 0; k4 < 16; k4++) {   // residual (reload input; L2-hot)
        float4 xv = xr4[k4];
        x1[4*k4+0] += xv.x; x1[4*k4+1] += xv.y; x1[4*k4+2] += xv.z; x1[4*k4+3] += xv.w;
    }
    layernorm64(x1, g1, be1);
    __syncthreads();

    // ---- FFN up: h = gelu(x1 @ W_ff1 + b_ff1) -> own smem row ----
    for (int i = t; i < 2048; i += 256) ((float4*)sw)[i] = ((const float4*)Wf1)[i];
    __syncthreads();
    float* hrow = sH + t*SH_STRIDE;
    #pragma unroll
    for (int ch = 0; ch < 4; ch++) {
        ull acc[16];
        const ull* bp = (const ull*)(bf1 + ch*32);
        #pragma unroll
        for (int j = 0; j < 16; j++) acc[j] = bp[j];
        gemm64p(x1, sw, 128, ch*32, acc);
        #pragma unroll
        for (int j = 0; j < 16; j++) {
            float2 v = unpack2(acc[j]);
            hrow[ch*32 + 2*j + 0] = 0.5f*v.x*(1.f + erff(v.x*0.70710678118654752f));
            hrow[ch*32 + 2*j + 1] = 0.5f*v.y*(1.f + erff(v.y*0.70710678118654752f));
        }
    }
    __syncthreads();

    // ---- FFN down + residual + LN2 ----
    for (int i = t; i < 2048; i += 256) ((float4*)sw)[i] = ((const float4*)Wf2)[i];
    __syncthreads();
    float x2[64];
    #pragma unroll
    for (int ch = 0; ch < 2; ch++) {
        ull acc[16];
        const ull* bp = (const ull*)(bf2 + ch*32);
        #pragma unroll
        for (int j = 0; j < 16; j++) acc[j] = bp[j];
        #pragma unroll 4
        for (int k = 0; k < 128; k++) {
            ull hp = pack2(hrow[k]);
            const ulonglong2* wr = (const ulonglong2*)(sw + k*64 + ch*32);
            #pragma unroll
            for (int j = 0; j < 8; j++) {
                ulonglong2 w = wr[j];
                acc[2*j+0] = ffma2(hp, w.x, acc[2*j+0]);
                acc[2*j+1] = ffma2(hp, w.y, acc[2*j+1]);
            }
        }
        #pragma unroll
        for (int j = 0; j < 16; j++) {
            float2 v = unpack2(acc[j]);
            x2[ch*32 + 2*j + 0] = v.x + x1[ch*32 + 2*j + 0];
            x2[ch*32 + 2*j + 1] = v.y + x1[ch*32 + 2*j + 1];
        }
    }
    layernorm64(x2, g2, be2);
    __syncthreads();

    // ---- classifier + log_softmax ----
    for (int i = t; i < 256; i += 256) ((float4*)sw)[i] = ((const float4*)Wc)[i];
    __syncthreads();
    ull lg2[8];
    const ull* bcp = (const ull*)bc;
    #pragma unroll
    for (int j = 0; j < 8; j++) lg2[j] = bcp[j];
    #pragma unroll
    for (int k = 0; k < 64; k++) {
        ull xp = pack2(x2[k]);
        const ulonglong2* wr = (const ulonglong2*)(sw + k*16);
        #pragma unroll
        for (int j = 0; j < 4; j++) {
            ulonglong2 w = wr[j];
            lg2[2*j+0] = ffma2(xp, w.x, lg2[2*j+0]);
            lg2[2*j+1] = ffma2(xp, w.y, lg2[2*j+1]);
        }
    }
    float lg[16];
    #pragma unroll
    for (int j = 0; j < 8; j++) {
        float2 v = unpack2(lg2[j]);
        lg[2*j] = v.x; lg[2*j+1] = v.y;
    }
    float mm = lg[0];
    #pragma unroll
    for (int j = 1; j < 16; j++) mm = fmaxf(mm, lg[j]);
    float ssum = 0.f;
    #pragma unroll
    for (int j = 0; j < 16; j++) ssum += __expf(lg[j] - mm);
    float lse = mm + logf(ssum);
    float4* op = (float4*)(out + ((size_t)blk*256 + t)*16);
    #pragma unroll
    for (int j4 = 0; j4 < 4; j4++)
        op[j4] = make_float4(lg[4*j4]-lse, lg[4*j4+1]-lse, lg[4*j4+2]-lse, lg[4*j4+3]-lse);
}

// ---------------- launch ----------------
extern "C" void kernel_launch(void* const* d_in, const int* in_sizes, int n_in,
                              void* d_out, int out_size) {
    const float* x    = (const float*)d_in[0];
    const int*   rows = (const int*)  d_in[1];
    const int*   cols = (const int*)  d_in[2];
    const float* vals = (const float*)d_in[3];
    const float* W1   = (const float*)d_in[4];
    const float* b1   = (const float*)d_in[5];
    const float* W2   = (const float*)d_in[6];
    const float* b2   = (const float*)d_in[7];
    const float* Wqkv = (const float*)d_in[8];
    const float* bqkv = (const float*)d_in[9];
    const float* Wo   = (const float*)d_in[10];
    const float* bo   = (const float*)d_in[11];
    const float* g1   = (const float*)d_in[12];
    const float* be1  = (const float*)d_in[13];
    const float* Wf1  = (const float*)d_in[14];
    const float* bf1  = (const float*)d_in[15];
    const float* Wf2  = (const float*)d_in[16];
    const float* bf2  = (const float*)d_in[17];
    const float* g2   = (const float*)d_in[18];
    const float* be2  = (const float*)d_in[19];
    const float* Wc   = (const float*)d_in[20];
    const float* bc   = (const float*)d_in[21];
    float* out = (float*)d_out;

    static bool attr_set = false;
    if (!attr_set) {
        cudaFuncSetAttribute(k_tr, cudaFuncAttributeMaxDynamicSharedMemorySize, SMEM_BYTES);
        attr_set = true;
    }

    k_zero_cnt<<<NN/256, 256>>>();
    k_hist    <<<NNZE/256, 256>>>(rows);
    k_scan    <<<1, 1024>>>();
    k_scatter <<<NNZE/256, 256>>>(rows, cols, vals);
    k_xw1     <<<NN/256, 256>>>(x, W1);
    k_spmm1   <<<NN/8, 256>>>(b1);
    k_spmm2   <<<NN/8, 256>>>(W2, b2);
    k_tr      <<<NN/256, 256, SMEM_BYTES>>>(Wqkv, bqkv, Wo, bo, g1, be1,
                                            Wf1, bf1, Wf2, bf2, g2, be2,
                                            Wc, bc, out);
}